// round 3
// baseline (speedup 1.0000x reference)
#include <cuda_runtime.h>

#define N_NODES_MAX 100000
#define D_IN 512
#define D_HID 16

// Scratch buffers (device globals — no allocation allowed)
__device__ float g_h1[N_NODES_MAX * D_HID];    // x @ W1
__device__ float g_agg1[N_NODES_MAX * D_HID];  // scatter(h1) + b1
__device__ float g_h2[N_NODES_MAX * D_HID];    // relu(agg1) @ W2
__device__ int   g_idx64;                      // 1 if edge_index is int64

// ---------------------------------------------------------------------------
// Probe: detect edge_index element width. For int64 indices (< 2^31) every
// odd int32 word is zero; for random int32 indices 128 consecutive zeros at
// odd positions is (1/N_NODES)^128 ~ 0. Deterministic given fixed inputs.
// ---------------------------------------------------------------------------
__global__ void probe_idx_kernel(const int* __restrict__ ei_raw) {
    if (threadIdx.x == 0 && blockIdx.x == 0) {
        int all_zero = 1;
        for (int i = 1; i < 256; i += 2)
            if (ei_raw[i] != 0) { all_zero = 0; break; }
        g_idx64 = all_zero;
    }
}

// ---------------------------------------------------------------------------
// Init: agg1 <- b1 broadcast, out <- b2 broadcast
// ---------------------------------------------------------------------------
__global__ void init_bias_kernel(const float* __restrict__ b1,
                                 const float* __restrict__ b2,
                                 float* __restrict__ out, int n_nodes) {
    int i = blockIdx.x * blockDim.x + threadIdx.x;
    int total = n_nodes * D_HID;
    if (i < total) {
        int c = i & 15;
        g_agg1[i] = __ldg(b1 + c);
        out[i]    = __ldg(b2 + c);
    }
}

// ---------------------------------------------------------------------------
// GEMM1: h1[n, 16] = x[n, 512] @ W1[512, 16]
// Block = 128 threads, 256 rows/block (2 rows per thread), k-tile = 32.
// ---------------------------------------------------------------------------
#define ACC4(A, i, xv, W4)                        \
    A[(i)+0] = fmaf(xv, (W4).x, A[(i)+0]);        \
    A[(i)+1] = fmaf(xv, (W4).y, A[(i)+1]);        \
    A[(i)+2] = fmaf(xv, (W4).z, A[(i)+2]);        \
    A[(i)+3] = fmaf(xv, (W4).w, A[(i)+3]);

__global__ void __launch_bounds__(128) gemm1_kernel(
    const float* __restrict__ x,
    const float* __restrict__ W1,
    int n_nodes) {
    __shared__ float ws[32 * 16];        // 2 KB  (one k-tile of W1)
    __shared__ float xs[256 * 36];       // 36 KB (256 rows x 32 k, +4 pad)

    const int tid  = threadIdx.x;
    const int row0 = blockIdx.x * 256;

    float acc0[16], acc1[16];
#pragma unroll
    for (int c = 0; c < 16; c++) { acc0[c] = 0.f; acc1[c] = 0.f; }

    const int r_a = row0 + tid;
    const int r_b = row0 + tid + 128;

    for (int kt = 0; kt < D_IN; kt += 32) {
        __syncthreads();
        // W tile: 32 x 16 floats = 128 float4, one per thread
        {
            const float4 v = *((const float4*)(W1 + kt * 16) + tid);
            ((float4*)ws)[tid] = v;
        }
        // x tile: 256 rows x 32 floats = 2048 float4, 16 per thread
#pragma unroll
        for (int i = 0; i < 16; i++) {
            int lin  = i * 128 + tid;
            int r    = lin >> 3;   // 8 float4 per row
            int j    = lin & 7;
            int grow = row0 + r;
            float4 v = make_float4(0.f, 0.f, 0.f, 0.f);
            if (grow < n_nodes)
                v = *(const float4*)(x + (long)grow * D_IN + kt + j * 4);
            *(float4*)(xs + r * 36 + j * 4) = v;
        }
        __syncthreads();

#pragma unroll
        for (int j = 0; j < 8; j++) {
            float4 xa = *(const float4*)(xs + tid * 36 + j * 4);
            float4 xb = *(const float4*)(xs + (tid + 128) * 36 + j * 4);
#pragma unroll
            for (int kk = 0; kk < 4; kk++) {
                float va = (&xa.x)[kk];
                float vb = (&xb.x)[kk];
                const float4* wr = (const float4*)(ws + (j * 4 + kk) * 16);
                float4 wq0 = wr[0], wq1 = wr[1], wq2 = wr[2], wq3 = wr[3];
                ACC4(acc0, 0,  va, wq0); ACC4(acc0, 4,  va, wq1);
                ACC4(acc0, 8,  va, wq2); ACC4(acc0, 12, va, wq3);
                ACC4(acc1, 0,  vb, wq0); ACC4(acc1, 4,  vb, wq1);
                ACC4(acc1, 8,  vb, wq2); ACC4(acc1, 12, vb, wq3);
            }
        }
    }

    if (r_a < n_nodes) {
        float4* op = (float4*)(g_h1 + (long)r_a * 16);
        op[0] = make_float4(acc0[0],  acc0[1],  acc0[2],  acc0[3]);
        op[1] = make_float4(acc0[4],  acc0[5],  acc0[6],  acc0[7]);
        op[2] = make_float4(acc0[8],  acc0[9],  acc0[10], acc0[11]);
        op[3] = make_float4(acc0[12], acc0[13], acc0[14], acc0[15]);
    }
    if (r_b < n_nodes) {
        float4* op = (float4*)(g_h1 + (long)r_b * 16);
        op[0] = make_float4(acc1[0],  acc1[1],  acc1[2],  acc1[3]);
        op[1] = make_float4(acc1[4],  acc1[5],  acc1[6],  acc1[7]);
        op[2] = make_float4(acc1[8],  acc1[9],  acc1[10], acc1[11]);
        op[3] = make_float4(acc1[12], acc1[13], acc1[14], acc1[15]);
    }
}

// ---------------------------------------------------------------------------
// Weighted scatter-add: agg[dst[e]] += ew[e] * h[src[e]]  (16 floats/edge)
// red.global.add.v4.f32 (sm_90+): 4 vector reductions per edge instead of
// 16 scalar atomics. Index width selected at runtime via g_idx64.
// ---------------------------------------------------------------------------
__device__ __forceinline__ void red_add_v4(float* p, float a, float b, float c, float d) {
    asm volatile("red.global.add.v4.f32 [%0], {%1, %2, %3, %4};"
                 :: "l"(p), "f"(a), "f"(b), "f"(c), "f"(d) : "memory");
}

__global__ void scatter_kernel(const void* __restrict__ ei_raw,
                               const float* __restrict__ ew,
                               float* __restrict__ out,   // used when layer==1
                               int layer, int n_edges) {
    int e = blockIdx.x * blockDim.x + threadIdx.x;
    if (e >= n_edges) return;

    int s, d;
    if (g_idx64) {
        const long long* p = (const long long*)ei_raw;
        s = (int)__ldg(p + e);
        d = (int)__ldg(p + n_edges + e);
    } else {
        const int* p = (const int*)ei_raw;
        s = __ldg(p + e);
        d = __ldg(p + n_edges + e);
    }
    const float w = __ldg(ew + e);

    const float* h   = (layer == 0) ? g_h1   : g_h2;
    float*       agg = (layer == 0) ? g_agg1 : out;

    const float4* hp = (const float4*)(h + (long)s * 16);
    float4 m0 = hp[0], m1 = hp[1], m2 = hp[2], m3 = hp[3];

    float* ap = agg + (long)d * 16;
    red_add_v4(ap + 0,  m0.x * w, m0.y * w, m0.z * w, m0.w * w);
    red_add_v4(ap + 4,  m1.x * w, m1.y * w, m1.z * w, m1.w * w);
    red_add_v4(ap + 8,  m2.x * w, m2.y * w, m2.z * w, m2.w * w);
    red_add_v4(ap + 12, m3.x * w, m3.y * w, m3.z * w, m3.w * w);
}

// ---------------------------------------------------------------------------
// GEMM2 + relu: h2[n, 16] = relu(agg1[n, 16]) @ W2[16, 16]
// ---------------------------------------------------------------------------
__global__ void __launch_bounds__(256) gemm2_relu_kernel(
    const float* __restrict__ W2, int n_nodes) {
    __shared__ float w[256];
    w[threadIdx.x] = __ldg(W2 + threadIdx.x);
    __syncthreads();

    int n = blockIdx.x * blockDim.x + threadIdx.x;
    if (n >= n_nodes) return;

    const float4* ap = (const float4*)(g_agg1 + (long)n * 16);
    float v[16];
#pragma unroll
    for (int q = 0; q < 4; q++) {
        float4 t = ap[q];
        v[q * 4 + 0] = fmaxf(t.x, 0.f);
        v[q * 4 + 1] = fmaxf(t.y, 0.f);
        v[q * 4 + 2] = fmaxf(t.z, 0.f);
        v[q * 4 + 3] = fmaxf(t.w, 0.f);
    }

    float acc[16];
#pragma unroll
    for (int c = 0; c < 16; c++) acc[c] = 0.f;
#pragma unroll
    for (int k = 0; k < 16; k++) {
        float xv = v[k];
        const float4* wr = (const float4*)(w + k * 16);
        float4 wq0 = wr[0], wq1 = wr[1], wq2 = wr[2], wq3 = wr[3];
        ACC4(acc, 0,  xv, wq0); ACC4(acc, 4,  xv, wq1);
        ACC4(acc, 8,  xv, wq2); ACC4(acc, 12, xv, wq3);
    }

    float4* op = (float4*)(g_h2 + (long)n * 16);
    op[0] = make_float4(acc[0],  acc[1],  acc[2],  acc[3]);
    op[1] = make_float4(acc[4],  acc[5],  acc[6],  acc[7]);
    op[2] = make_float4(acc[8],  acc[9],  acc[10], acc[11]);
    op[3] = make_float4(acc[12], acc[13], acc[14], acc[15]);
}

// ---------------------------------------------------------------------------
// log_softmax (axis=1, width 16), in place on out
// ---------------------------------------------------------------------------
__global__ void logsoftmax_kernel(float* __restrict__ out, int n_nodes) {
    int n = blockIdx.x * blockDim.x + threadIdx.x;
    if (n >= n_nodes) return;

    float4* p = (float4*)(out + (long)n * 16);
    float v[16];
#pragma unroll
    for (int q = 0; q < 4; q++) {
        float4 t = p[q];
        v[q * 4 + 0] = t.x; v[q * 4 + 1] = t.y;
        v[q * 4 + 2] = t.z; v[q * 4 + 3] = t.w;
    }
    float mx = v[0];
#pragma unroll
    for (int c = 1; c < 16; c++) mx = fmaxf(mx, v[c]);
    float s = 0.f;
#pragma unroll
    for (int c = 0; c < 16; c++) s += expf(v[c] - mx);
    float lse = mx + logf(s);
#pragma unroll
    for (int q = 0; q < 4; q++) {
        p[q] = make_float4(v[q * 4 + 0] - lse, v[q * 4 + 1] - lse,
                           v[q * 4 + 2] - lse, v[q * 4 + 3] - lse);
    }
}

// ---------------------------------------------------------------------------
// Launch
// ---------------------------------------------------------------------------
extern "C" void kernel_launch(void* const* d_in, const int* in_sizes, int n_in,
                              void* d_out, int out_size) {
    const float* x   = (const float*)d_in[0];
    const void*  ei  = d_in[1];
    const float* ew  = (const float*)d_in[2];
    const float* W1  = (const float*)d_in[3];
    const float* b1  = (const float*)d_in[4];
    const float* W2  = (const float*)d_in[5];
    const float* b2  = (const float*)d_in[6];
    float*       out = (float*)d_out;

    const int n_nodes = in_sizes[0] / D_IN;
    const int n_edges = in_sizes[2];

    // 0. detect index width (int32 vs int64)
    probe_idx_kernel<<<1, 32>>>((const int*)ei);
    // 1. biases into agg1 / out
    init_bias_kernel<<<(n_nodes * D_HID + 255) / 256, 256>>>(b1, b2, out, n_nodes);
    // 2. h1 = x @ W1
    gemm1_kernel<<<(n_nodes + 255) / 256, 128>>>(x, W1, n_nodes);
    // 3. agg1 += scatter(ew * h1[src] -> dst)
    scatter_kernel<<<(n_edges + 255) / 256, 256>>>(ei, ew, out, 0, n_edges);
    // 4. h2 = relu(agg1) @ W2
    gemm2_relu_kernel<<<(n_nodes + 255) / 256, 256>>>(W2, n_nodes);
    // 5. out += scatter(ew * h2[src] -> dst)
    scatter_kernel<<<(n_edges + 255) / 256, 256>>>(ei, ew, out, 1, n_edges);
    // 6. log_softmax rows of out, in place
    logsoftmax_kernel<<<(n_nodes + 255) / 256, 256>>>(out, n_nodes);
}

// round 4
// speedup vs baseline: 1.4024x; 1.4024x over previous
#include <cuda_runtime.h>

#define N_NODES_MAX 100000
#define D_IN 512
#define D_HID 16

// Scratch buffers (device globals — no allocation allowed)
__device__ float g_h1[N_NODES_MAX * D_HID];    // x @ W1
__device__ float g_agg1[N_NODES_MAX * D_HID];  // scatter(h1) + b1
__device__ float g_h2[N_NODES_MAX * D_HID];    // relu(agg1) @ W2
__device__ int   g_idx64;                      // 1 if edge_index is int64

// ---------------------------------------------------------------------------
// Probe: detect edge_index element width. For int64 indices (< 2^31) every
// odd int32 word is zero; for random int32 indices 128 consecutive zeros at
// odd positions is (1/N_NODES)^128 ~ 0. Deterministic given fixed inputs.
// ---------------------------------------------------------------------------
__global__ void probe_idx_kernel(const int* __restrict__ ei_raw) {
    if (threadIdx.x == 0 && blockIdx.x == 0) {
        int all_zero = 1;
        for (int i = 1; i < 256; i += 2)
            if (ei_raw[i] != 0) { all_zero = 0; break; }
        g_idx64 = all_zero;
    }
}

// ---------------------------------------------------------------------------
// Init: agg1 <- b1 broadcast, out <- b2 broadcast
// ---------------------------------------------------------------------------
__global__ void init_bias_kernel(const float* __restrict__ b1,
                                 const float* __restrict__ b2,
                                 float* __restrict__ out, int n_nodes) {
    int i = blockIdx.x * blockDim.x + threadIdx.x;
    int total = n_nodes * D_HID;
    if (i < total) {
        int c = i & 15;
        g_agg1[i] = __ldg(b1 + c);
        out[i]    = __ldg(b2 + c);
    }
}

// ---------------------------------------------------------------------------
// GEMM1: h1[n, 16] = x[n, 512] @ W1[512, 16]
// Block = 128 threads, 256 rows/block (2 rows per thread), k-tile = 32.
// ---------------------------------------------------------------------------
#define ACC4(A, i, xv, W4)                        \
    A[(i)+0] = fmaf(xv, (W4).x, A[(i)+0]);        \
    A[(i)+1] = fmaf(xv, (W4).y, A[(i)+1]);        \
    A[(i)+2] = fmaf(xv, (W4).z, A[(i)+2]);        \
    A[(i)+3] = fmaf(xv, (W4).w, A[(i)+3]);

__global__ void __launch_bounds__(128) gemm1_kernel(
    const float* __restrict__ x,
    const float* __restrict__ W1,
    int n_nodes) {
    __shared__ float ws[32 * 16];        // 2 KB  (one k-tile of W1)
    __shared__ float xs[256 * 36];       // 36 KB (256 rows x 32 k, +4 pad)

    const int tid  = threadIdx.x;
    const int row0 = blockIdx.x * 256;

    float acc0[16], acc1[16];
#pragma unroll
    for (int c = 0; c < 16; c++) { acc0[c] = 0.f; acc1[c] = 0.f; }

    const int r_a = row0 + tid;
    const int r_b = row0 + tid + 128;

    for (int kt = 0; kt < D_IN; kt += 32) {
        __syncthreads();
        // W tile: 32 x 16 floats = 128 float4, one per thread
        {
            const float4 v = *((const float4*)(W1 + kt * 16) + tid);
            ((float4*)ws)[tid] = v;
        }
        // x tile: 256 rows x 32 floats = 2048 float4, 16 per thread
#pragma unroll
        for (int i = 0; i < 16; i++) {
            int lin  = i * 128 + tid;
            int r    = lin >> 3;   // 8 float4 per row
            int j    = lin & 7;
            int grow = row0 + r;
            float4 v = make_float4(0.f, 0.f, 0.f, 0.f);
            if (grow < n_nodes)
                v = *(const float4*)(x + (long)grow * D_IN + kt + j * 4);
            *(float4*)(xs + r * 36 + j * 4) = v;
        }
        __syncthreads();

#pragma unroll
        for (int j = 0; j < 8; j++) {
            float4 xa = *(const float4*)(xs + tid * 36 + j * 4);
            float4 xb = *(const float4*)(xs + (tid + 128) * 36 + j * 4);
#pragma unroll
            for (int kk = 0; kk < 4; kk++) {
                float va = (&xa.x)[kk];
                float vb = (&xb.x)[kk];
                const float4* wr = (const float4*)(ws + (j * 4 + kk) * 16);
                float4 wq0 = wr[0], wq1 = wr[1], wq2 = wr[2], wq3 = wr[3];
                ACC4(acc0, 0,  va, wq0); ACC4(acc0, 4,  va, wq1);
                ACC4(acc0, 8,  va, wq2); ACC4(acc0, 12, va, wq3);
                ACC4(acc1, 0,  vb, wq0); ACC4(acc1, 4,  vb, wq1);
                ACC4(acc1, 8,  vb, wq2); ACC4(acc1, 12, vb, wq3);
            }
        }
    }

    if (r_a < n_nodes) {
        float4* op = (float4*)(g_h1 + (long)r_a * 16);
        op[0] = make_float4(acc0[0],  acc0[1],  acc0[2],  acc0[3]);
        op[1] = make_float4(acc0[4],  acc0[5],  acc0[6],  acc0[7]);
        op[2] = make_float4(acc0[8],  acc0[9],  acc0[10], acc0[11]);
        op[3] = make_float4(acc0[12], acc0[13], acc0[14], acc0[15]);
    }
    if (r_b < n_nodes) {
        float4* op = (float4*)(g_h1 + (long)r_b * 16);
        op[0] = make_float4(acc1[0],  acc1[1],  acc1[2],  acc1[3]);
        op[1] = make_float4(acc1[4],  acc1[5],  acc1[6],  acc1[7]);
        op[2] = make_float4(acc1[8],  acc1[9],  acc1[10], acc1[11]);
        op[3] = make_float4(acc1[12], acc1[13], acc1[14], acc1[15]);
    }
}

// ---------------------------------------------------------------------------
// Weighted scatter-add, 4 lanes per edge:
//   lane q of edge e handles float4 quarter q of the 16-wide row.
// Gather LDG.128 is 64B-contiguous per edge (8 edges/warp -> ~8 wavefronts
// per instruction instead of 32), index/weight loads are warp-coalesced
// broadcasts. red.global.add.v4.f32 per lane.
// ---------------------------------------------------------------------------
__device__ __forceinline__ void red_add_v4(float* p, float a, float b, float c, float d) {
    asm volatile("red.global.add.v4.f32 [%0], {%1, %2, %3, %4};"
                 :: "l"(p), "f"(a), "f"(b), "f"(c), "f"(d) : "memory");
}

__global__ void __launch_bounds__(256) scatter_kernel(
    const void* __restrict__ ei_raw,
    const float* __restrict__ ew,
    float* __restrict__ out,   // used when layer==1
    int layer, int n_edges) {
    int t = blockIdx.x * blockDim.x + threadIdx.x;
    int e = t >> 2;
    int q = t & 3;
    if (e >= n_edges) return;

    int s, d;
    if (g_idx64) {
        const long long* p = (const long long*)ei_raw;
        s = (int)__ldg(p + e);
        d = (int)__ldg(p + n_edges + e);
    } else {
        const int* p = (const int*)ei_raw;
        s = __ldg(p + e);
        d = __ldg(p + n_edges + e);
    }
    const float w = __ldg(ew + e);

    const float* h   = (layer == 0) ? g_h1   : g_h2;
    float*       agg = (layer == 0) ? g_agg1 : out;

    float4 m = __ldg((const float4*)(h + (long)s * 16) + q);
    red_add_v4(agg + (long)d * 16 + q * 4, m.x * w, m.y * w, m.z * w, m.w * w);
}

// ---------------------------------------------------------------------------
// GEMM2 + relu: h2[n, 16] = relu(agg1[n, 16]) @ W2[16, 16]
// ---------------------------------------------------------------------------
__global__ void __launch_bounds__(256) gemm2_relu_kernel(
    const float* __restrict__ W2, int n_nodes) {
    __shared__ float w[256];
    w[threadIdx.x] = __ldg(W2 + threadIdx.x);
    __syncthreads();

    int n = blockIdx.x * blockDim.x + threadIdx.x;
    if (n >= n_nodes) return;

    const float4* ap = (const float4*)(g_agg1 + (long)n * 16);
    float v[16];
#pragma unroll
    for (int q = 0; q < 4; q++) {
        float4 t = ap[q];
        v[q * 4 + 0] = fmaxf(t.x, 0.f);
        v[q * 4 + 1] = fmaxf(t.y, 0.f);
        v[q * 4 + 2] = fmaxf(t.z, 0.f);
        v[q * 4 + 3] = fmaxf(t.w, 0.f);
    }

    float acc[16];
#pragma unroll
    for (int c = 0; c < 16; c++) acc[c] = 0.f;
#pragma unroll
    for (int k = 0; k < 16; k++) {
        float xv = v[k];
        const float4* wr = (const float4*)(w + k * 16);
        float4 wq0 = wr[0], wq1 = wr[1], wq2 = wr[2], wq3 = wr[3];
        ACC4(acc, 0,  xv, wq0); ACC4(acc, 4,  xv, wq1);
        ACC4(acc, 8,  xv, wq2); ACC4(acc, 12, xv, wq3);
    }

    float4* op = (float4*)(g_h2 + (long)n * 16);
    op[0] = make_float4(acc[0],  acc[1],  acc[2],  acc[3]);
    op[1] = make_float4(acc[4],  acc[5],  acc[6],  acc[7]);
    op[2] = make_float4(acc[8],  acc[9],  acc[10], acc[11]);
    op[3] = make_float4(acc[12], acc[13], acc[14], acc[15]);
}

// ---------------------------------------------------------------------------
// log_softmax (axis=1, width 16), in place on out
// ---------------------------------------------------------------------------
__global__ void logsoftmax_kernel(float* __restrict__ out, int n_nodes) {
    int n = blockIdx.x * blockDim.x + threadIdx.x;
    if (n >= n_nodes) return;

    float4* p = (float4*)(out + (long)n * 16);
    float v[16];
#pragma unroll
    for (int q = 0; q < 4; q++) {
        float4 t = p[q];
        v[q * 4 + 0] = t.x; v[q * 4 + 1] = t.y;
        v[q * 4 + 2] = t.z; v[q * 4 + 3] = t.w;
    }
    float mx = v[0];
#pragma unroll
    for (int c = 1; c < 16; c++) mx = fmaxf(mx, v[c]);
    float s = 0.f;
#pragma unroll
    for (int c = 0; c < 16; c++) s += expf(v[c] - mx);
    float lse = mx + logf(s);
#pragma unroll
    for (int q = 0; q < 4; q++) {
        p[q] = make_float4(v[q * 4 + 0] - lse, v[q * 4 + 1] - lse,
                           v[q * 4 + 2] - lse, v[q * 4 + 3] - lse);
    }
}

// ---------------------------------------------------------------------------
// Launch
// ---------------------------------------------------------------------------
extern "C" void kernel_launch(void* const* d_in, const int* in_sizes, int n_in,
                              void* d_out, int out_size) {
    const float* x   = (const float*)d_in[0];
    const void*  ei  = d_in[1];
    const float* ew  = (const float*)d_in[2];
    const float* W1  = (const float*)d_in[3];
    const float* b1  = (const float*)d_in[4];
    const float* W2  = (const float*)d_in[5];
    const float* b2  = (const float*)d_in[6];
    float*       out = (float*)d_out;

    const int n_nodes = in_sizes[0] / D_IN;
    const int n_edges = in_sizes[2];
    const long long scat_threads = (long long)n_edges * 4;
    const int scat_blocks = (int)((scat_threads + 255) / 256);

    // 0. detect index width (int32 vs int64)
    probe_idx_kernel<<<1, 32>>>((const int*)ei);
    // 1. biases into agg1 / out
    init_bias_kernel<<<(n_nodes * D_HID + 255) / 256, 256>>>(b1, b2, out, n_nodes);
    // 2. h1 = x @ W1
    gemm1_kernel<<<(n_nodes + 255) / 256, 128>>>(x, W1, n_nodes);
    // 3. agg1 += scatter(ew * h1[src] -> dst)
    scatter_kernel<<<scat_blocks, 256>>>(ei, ew, out, 0, n_edges);
    // 4. h2 = relu(agg1) @ W2
    gemm2_relu_kernel<<<(n_nodes + 255) / 256, 256>>>(W2, n_nodes);
    // 5. out += scatter(ew * h2[src] -> dst)
    scatter_kernel<<<scat_blocks, 256>>>(ei, ew, out, 1, n_edges);
    // 6. log_softmax rows of out, in place
    logsoftmax_kernel<<<(n_nodes + 255) / 256, 256>>>(out, n_nodes);
}